// round 4
// baseline (speedup 1.0000x reference)
#include <cuda_runtime.h>
#include <cuda_bf16.h>
#include <math.h>
#include <stdint.h>

#define D_MODEL   1024
#define NUM_HEADS 16
#define HEAD_DIM  64
#define NTOK      4096
// (1/sqrt(64)) * log2(e)
#define C_SCALE   0.18033688011112042f

// ---------------- static scratch (allocation-free rule) ----------------
__device__ float g_v[NTOK * D_MODEL];
__device__ float g_o[NTOK * D_MODEL];

__device__ __nv_bfloat16 g_xh[NTOK * D_MODEL];
__device__ __nv_bfloat16 g_xl[NTOK * D_MODEL];
__device__ __nv_bfloat16 g_qh[NTOK * D_MODEL];
__device__ __nv_bfloat16 g_ql[NTOK * D_MODEL];
__device__ __nv_bfloat16 g_kh[NTOK * D_MODEL];
__device__ __nv_bfloat16 g_kl[NTOK * D_MODEL];
__device__ __nv_bfloat16 g_vh[NTOK * D_MODEL];
__device__ __nv_bfloat16 g_vl[NTOK * D_MODEL];
__device__ __nv_bfloat16 g_oh[NTOK * D_MODEL];
__device__ __nv_bfloat16 g_ol[NTOK * D_MODEL];
__device__ __nv_bfloat16 g_wqh[D_MODEL * D_MODEL];
__device__ __nv_bfloat16 g_wql[D_MODEL * D_MODEL];
__device__ __nv_bfloat16 g_wkh[D_MODEL * D_MODEL];
__device__ __nv_bfloat16 g_wkl[D_MODEL * D_MODEL];
__device__ __nv_bfloat16 g_wvh[D_MODEL * D_MODEL];
__device__ __nv_bfloat16 g_wvl[D_MODEL * D_MODEL];
__device__ __nv_bfloat16 g_woh[D_MODEL * D_MODEL];
__device__ __nv_bfloat16 g_wol[D_MODEL * D_MODEL];

// ---------------- helpers ----------------
__device__ __forceinline__ uint32_t smem_u32(const void* p) {
    uint32_t a;
    asm("{ .reg .u64 t; cvta.to.shared.u64 t, %1; cvt.u32.u64 %0, t; }"
        : "=r"(a) : "l"(p));
    return a;
}

__device__ __forceinline__ void ldsm_x4(uint32_t* r, uint32_t addr) {
    asm volatile("ldmatrix.sync.aligned.m8n8.x4.shared.b16 {%0,%1,%2,%3}, [%4];"
                 : "=r"(r[0]), "=r"(r[1]), "=r"(r[2]), "=r"(r[3]) : "r"(addr));
}
__device__ __forceinline__ void ldsm_x4t(uint32_t* r, uint32_t addr) {
    asm volatile("ldmatrix.sync.aligned.m8n8.x4.trans.shared.b16 {%0,%1,%2,%3}, [%4];"
                 : "=r"(r[0]), "=r"(r[1]), "=r"(r[2]), "=r"(r[3]) : "r"(addr));
}
__device__ __forceinline__ void mma_bf16(float* d, const uint32_t* a, const uint32_t* b) {
    asm volatile(
        "mma.sync.aligned.m16n8k16.row.col.f32.bf16.bf16.f32 "
        "{%0,%1,%2,%3}, {%4,%5,%6,%7}, {%8,%9}, {%0,%1,%2,%3};"
        : "+f"(d[0]), "+f"(d[1]), "+f"(d[2]), "+f"(d[3])
        : "r"(a[0]), "r"(a[1]), "r"(a[2]), "r"(a[3]), "r"(b[0]), "r"(b[1]));
}

#define CP_ASYNC16(dst, src) \
    asm volatile("cp.async.cg.shared.global [%0], [%1], 16;" :: "r"(dst), "l"(src))
#define CP_COMMIT asm volatile("cp.async.commit_group;" ::: "memory")
template <int N>
__device__ __forceinline__ void cp_wait() {
    asm volatile("cp.async.wait_group %0;" :: "n"(N) : "memory");
}

__device__ __forceinline__ uint32_t pack_bf16x2(float lo, float hi) {
    __nv_bfloat162 t = __floats2bfloat162_rn(lo, hi);
    return *(uint32_t*)&t;
}
__device__ __forceinline__ float bf16lo(uint32_t p) { return __uint_as_float(p << 16); }
__device__ __forceinline__ float bf16hi(uint32_t p) { return __uint_as_float(p & 0xffff0000u); }

// fast 2^t on FMA pipe (t <= 0 expected), rel err < 2e-5
__device__ __forceinline__ float exp2_fast(float t) {
    t = fmaxf(t, -126.0f);
    float fn = floorf(t);
    float f = t - fn;
    float p = fmaf(f, 0.000154035f, 0.0013333558f);
    p = fmaf(f, p, 0.0096181291f);
    p = fmaf(f, p, 0.0555041087f);
    p = fmaf(f, p, 0.2402265070f);
    p = fmaf(f, p, 0.6931471806f);
    p = fmaf(f, p, 1.0f);
    int n = (int)fn;
    return p * __int_as_float((n + 127) << 23);
}

// ---------------------------------------------------------------------------
// fp32 -> (bf16 hi, bf16 lo) split
// ---------------------------------------------------------------------------
__device__ __forceinline__ void split_body(const float* __restrict__ x,
                                           __nv_bfloat16* __restrict__ h,
                                           __nv_bfloat16* __restrict__ l, int i) {
    float4 v = *(const float4*)(x + i);
    __nv_bfloat16 h0 = __float2bfloat16(v.x);
    __nv_bfloat16 h1 = __float2bfloat16(v.y);
    __nv_bfloat16 h2 = __float2bfloat16(v.z);
    __nv_bfloat16 h3 = __float2bfloat16(v.w);
    __nv_bfloat16 l0 = __float2bfloat16(v.x - __bfloat162float(h0));
    __nv_bfloat16 l1 = __float2bfloat16(v.y - __bfloat162float(h1));
    __nv_bfloat16 l2 = __float2bfloat16(v.z - __bfloat162float(h2));
    __nv_bfloat16 l3 = __float2bfloat16(v.w - __bfloat162float(h3));
    __nv_bfloat162* hp = (__nv_bfloat162*)(h + i);
    __nv_bfloat162* lp = (__nv_bfloat162*)(l + i);
    hp[0] = __nv_bfloat162(h0, h1); hp[1] = __nv_bfloat162(h2, h3);
    lp[0] = __nv_bfloat162(l0, l1); lp[1] = __nv_bfloat162(l2, l3);
}

__global__ void split_bf16(const float* __restrict__ x, __nv_bfloat16* __restrict__ h,
                           __nv_bfloat16* __restrict__ l, int n) {
    int i = (blockIdx.x * blockDim.x + threadIdx.x) * 4;
    if (i < n) split_body(x, h, l, i);
}

// all four weight matrices in one launch (blockIdx.y selects the matrix)
__global__ void split_bf16_w4(const float* w0, const float* w1, const float* w2,
                              const float* w3, __nv_bfloat16* h0, __nv_bfloat16* l0,
                              __nv_bfloat16* h1, __nv_bfloat16* l1,
                              __nv_bfloat16* h2, __nv_bfloat16* l2,
                              __nv_bfloat16* h3, __nv_bfloat16* l3, int n) {
    const float* w[4] = {w0, w1, w2, w3};
    __nv_bfloat16* h[4] = {h0, h1, h2, h3};
    __nv_bfloat16* l[4] = {l0, l1, l2, l3};
    int m = blockIdx.y;
    int i = (blockIdx.x * blockDim.x + threadIdx.x) * 4;
    if (i < n) split_body(w[m], h[m], l[m], i);
}

// ---------------------------------------------------------------------------
// HMMA split-bf16 GEMM (unchanged from R3 — known good)
// ---------------------------------------------------------------------------
#define GSTAGE 40960
#define GTILE  10240

__global__ __launch_bounds__(256)
void gemm_mma(const __nv_bfloat16* __restrict__ Ah, const __nv_bfloat16* __restrict__ Al,
              const __nv_bfloat16* __restrict__ Bh, const __nv_bfloat16* __restrict__ Bl,
              float* __restrict__ C, __nv_bfloat16* __restrict__ Ch,
              __nv_bfloat16* __restrict__ Cl, int M, int N, int K) {
    extern __shared__ char smem[];
    const uint32_t sb = smem_u32(smem);
    const int tid = threadIdx.x;
    const int lane = tid & 31;
    const int wid = tid >> 5;
    const int wm = wid & 3;
    const int wn = wid >> 2;
    const int m0 = blockIdx.y * 128;
    const int n0 = blockIdx.x * 128;

    const __nv_bfloat16* srcs[4] = {Ah + (size_t)m0 * K, Al + (size_t)m0 * K,
                                    Bh + (size_t)n0 * K, Bl + (size_t)n0 * K};

    float acc[2][8][4];
#pragma unroll
    for (int a = 0; a < 2; a++)
#pragma unroll
        for (int b = 0; b < 8; b++)
#pragma unroll
            for (int c = 0; c < 4; c++) acc[a][b][c] = 0.f;

    auto load_stage = [&](int s, int kc) {
        uint32_t base = sb + s * GSTAGE;
#pragma unroll
        for (int t = 0; t < 4; t++) {
#pragma unroll
            for (int i = 0; i < 2; i++) {
                int seg = tid + i * 256;
                int row = seg >> 2;
                int cs = seg & 3;
                const void* src = srcs[t] + (size_t)row * K + kc * 32 + cs * 8;
                uint32_t dst = base + t * GTILE + (row * 40 + cs * 8) * 2;
                CP_ASYNC16(dst, src);
            }
        }
    };

    const int NCH = K / 32;
    load_stage(0, 0);
    CP_COMMIT;

    for (int kc = 0; kc < NCH; kc++) {
        if (kc + 1 < NCH) {
            load_stage((kc + 1) & 1, kc + 1);
            CP_COMMIT;
            cp_wait<1>();
        } else {
            cp_wait<0>();
        }
        __syncthreads();

        const uint32_t st = sb + (kc & 1) * GSTAGE;
#pragma unroll
        for (int kk = 0; kk < 32; kk += 16) {
            uint32_t a_h[2][4], a_l[2][4];
#pragma unroll
            for (int mt = 0; mt < 2; mt++) {
                uint32_t ar = st + ((wm * 32 + mt * 16 + (lane & 15)) * 40
                                    + kk + (lane >> 4) * 8) * 2;
                ldsm_x4(a_h[mt], ar);
                ldsm_x4(a_l[mt], ar + GTILE);
            }
#pragma unroll
            for (int np = 0; np < 4; np++) {
                uint32_t br = st + 2 * GTILE
                            + ((wn * 64 + np * 16 + ((lane >> 4) << 3) + (lane & 7)) * 40
                               + kk + ((lane >> 3) & 1) * 8) * 2;
                uint32_t bh[4], bl[4];
                ldsm_x4(bh, br);
                ldsm_x4(bl, br + GTILE);
#pragma unroll
                for (int mt = 0; mt < 2; mt++) {
                    mma_bf16(acc[mt][2 * np],     a_h[mt], bh);
                    mma_bf16(acc[mt][2 * np],     a_h[mt], bl);
                    mma_bf16(acc[mt][2 * np],     a_l[mt], bh);
                    mma_bf16(acc[mt][2 * np + 1], a_h[mt], bh + 2);
                    mma_bf16(acc[mt][2 * np + 1], a_h[mt], bl + 2);
                    mma_bf16(acc[mt][2 * np + 1], a_l[mt], bh + 2);
                }
            }
        }
        __syncthreads();
    }

#pragma unroll
    for (int mt = 0; mt < 2; mt++) {
#pragma unroll
        for (int nt = 0; nt < 8; nt++) {
            int r0 = m0 + wm * 32 + mt * 16 + (lane >> 2);
            int col = n0 + wn * 64 + nt * 8 + (lane & 3) * 2;
            float d0 = acc[mt][nt][0], d1 = acc[mt][nt][1];
            float d2 = acc[mt][nt][2], d3 = acc[mt][nt][3];
            if (C) {
                float2 v0 = {d0, d1}, v1 = {d2, d3};
                *(float2*)&C[(size_t)r0 * N + col] = v0;
                *(float2*)&C[(size_t)(r0 + 8) * N + col] = v1;
            }
            if (Ch) {
                uint32_t ph0 = pack_bf16x2(d0, d1);
                uint32_t pl0 = pack_bf16x2(d0 - bf16lo(ph0), d1 - bf16hi(ph0));
                uint32_t ph1 = pack_bf16x2(d2, d3);
                uint32_t pl1 = pack_bf16x2(d2 - bf16lo(ph1), d3 - bf16hi(ph1));
                *(uint32_t*)&Ch[(size_t)r0 * N + col] = ph0;
                *(uint32_t*)&Cl[(size_t)r0 * N + col] = pl0;
                *(uint32_t*)&Ch[(size_t)(r0 + 8) * N + col] = ph1;
                *(uint32_t*)&Cl[(size_t)(r0 + 8) * N + col] = pl1;
            }
        }
    }
}

// ---------------------------------------------------------------------------
// HMMA flash attention v2: 128-query blocks, 256 thr (8 warps x 16 rows),
// 2-stage cp.async pipeline on K/V hi/lo tiles, split-bf16 QK^T and PV.
// ---------------------------------------------------------------------------
#define ABUF      9216          // 64 rows * 72 halves * 2B
#define ASTAGE    (4 * ABUF)    // Kh, Kl, Vh, Vl
#define ATT_SMEM  (2 * ASTAGE)  // 73728

__global__ __launch_bounds__(256)
void attn_mma(const __nv_bfloat16* __restrict__ Qh_, const __nv_bfloat16* __restrict__ Ql_,
              const __nv_bfloat16* __restrict__ Kh_, const __nv_bfloat16* __restrict__ Kl_,
              const __nv_bfloat16* __restrict__ Vh_, const __nv_bfloat16* __restrict__ Vl_,
              float* __restrict__ O, int S) {
    extern __shared__ char smem[];
    const uint32_t sb = smem_u32(smem);

    const int tid = threadIdx.x;
    const int lane = tid & 31;
    const int wid = tid >> 5;          // 0..7
    const int h = blockIdx.y;
    const int b = blockIdx.z;
    const int q0 = blockIdx.x * 128;
    const int tok0 = b * S;
    const int hoff = h * HEAD_DIM;

    // ---- stage Q hi/lo (128 rows) through the Kh/Kl buffers of both stages ----
#pragma unroll
    for (int i = 0; i < 4; i++) {
        int seg = tid + i * 256;       // 0..1023
        int row = seg >> 3;            // 0..127
        int cs = seg & 7;
        int st = row >> 6;             // stage 0 holds rows 0-63, stage 1 rows 64-127
        int lr = row & 63;
        size_t g = (size_t)(tok0 + q0 + row) * D_MODEL + hoff + cs * 8;
        uint32_t d = st * ASTAGE + (lr * 72 + cs * 8) * 2;
        CP_ASYNC16(sb + d, Qh_ + g);
        CP_ASYNC16(sb + d + ABUF, Ql_ + g);
    }
    CP_COMMIT;
    cp_wait<0>();
    __syncthreads();

    uint32_t qh[4][4], ql[4][4];
    {
        int row = wid * 16 + (lane & 15);     // 0..127
        int st = row >> 6;
        int lr = row & 63;
#pragma unroll
        for (int kt = 0; kt < 4; kt++) {
            uint32_t off = st * ASTAGE + (lr * 72 + kt * 16 + (lane >> 4) * 8) * 2;
            ldsm_x4(qh[kt], sb + off);
            ldsm_x4(ql[kt], sb + off + ABUF);
        }
    }
    __syncthreads();

    float acc_o[8][4];
#pragma unroll
    for (int i = 0; i < 8; i++)
#pragma unroll
        for (int j = 0; j < 4; j++) acc_o[i][j] = 0.f;
    float mA = -1e30f, mB = -1e30f, lA = 0.f, lB = 0.f;

    auto load_kv = [&](int s, int c0) {
        uint32_t base = sb + s * ASTAGE;
#pragma unroll
        for (int i = 0; i < 2; i++) {
            int seg = tid + i * 256;   // 0..511
            int row = seg >> 3;        // 0..63
            int cs = seg & 7;
            size_t g = (size_t)(tok0 + c0 + row) * D_MODEL + hoff + cs * 8;
            uint32_t d = base + (row * 72 + cs * 8) * 2;
            CP_ASYNC16(d, Kh_ + g);
            CP_ASYNC16(d + ABUF, Kl_ + g);
            CP_ASYNC16(d + 2 * ABUF, Vh_ + g);
            CP_ASYNC16(d + 3 * ABUF, Vl_ + g);
        }
    };

    const int NIT = S / 64;    // 32
    load_kv(0, 0);
    CP_COMMIT;

    for (int it = 0; it < NIT; it++) {
        if (it + 1 < NIT) {
            load_kv((it + 1) & 1, (it + 1) * 64);
            CP_COMMIT;
            cp_wait<1>();
        } else {
            cp_wait<0>();
        }
        __syncthreads();

        const uint32_t st = sb + (it & 1) * ASTAGE;

        // ---- S = Q K^T (split, 3 passes) ----
        float s[8][4];
#pragma unroll
        for (int i = 0; i < 8; i++)
#pragma unroll
            for (int j = 0; j < 4; j++) s[i][j] = 0.f;

#pragma unroll
        for (int kt = 0; kt < 4; kt++) {
#pragma unroll
            for (int np = 0; np < 4; np++) {
                uint32_t off = st + ((np * 16 + ((lane >> 4) << 3) + (lane & 7)) * 72
                                     + kt * 16 + ((lane >> 3) & 1) * 8) * 2;
                uint32_t bh[4], bl[4];
                ldsm_x4(bh, off);
                ldsm_x4(bl, off + ABUF);
                mma_bf16(s[2 * np],     qh[kt], bh);
                mma_bf16(s[2 * np],     qh[kt], bl);
                mma_bf16(s[2 * np],     ql[kt], bh);
                mma_bf16(s[2 * np + 1], qh[kt], bh + 2);
                mma_bf16(s[2 * np + 1], qh[kt], bl + 2);
                mma_bf16(s[2 * np + 1], ql[kt], bh + 2);
            }
        }

        // ---- online softmax (log2 domain) ----
        float mxA = -1e30f, mxB = -1e30f;
#pragma unroll
        for (int nt = 0; nt < 8; nt++) {
            s[nt][0] *= C_SCALE; s[nt][1] *= C_SCALE;
            s[nt][2] *= C_SCALE; s[nt][3] *= C_SCALE;
            mxA = fmaxf(mxA, fmaxf(s[nt][0], s[nt][1]));
            mxB = fmaxf(mxB, fmaxf(s[nt][2], s[nt][3]));
        }
        mxA = fmaxf(mxA, __shfl_xor_sync(0xffffffffu, mxA, 1));
        mxA = fmaxf(mxA, __shfl_xor_sync(0xffffffffu, mxA, 2));
        mxB = fmaxf(mxB, __shfl_xor_sync(0xffffffffu, mxB, 1));
        mxB = fmaxf(mxB, __shfl_xor_sync(0xffffffffu, mxB, 2));
        float mAn = fmaxf(mA, mxA);
        float mBn = fmaxf(mB, mxB);
        float facA = exp2_fast(mA - mAn);
        float facB = exp2_fast(mB - mBn);
        float sumA = 0.f, sumB = 0.f;
#pragma unroll
        for (int nt = 0; nt < 8; nt++) {
            s[nt][0] = exp2_fast(s[nt][0] - mAn);
            s[nt][1] = exp2_fast(s[nt][1] - mAn);
            s[nt][2] = exp2_fast(s[nt][2] - mBn);
            s[nt][3] = exp2_fast(s[nt][3] - mBn);
            sumA += s[nt][0] + s[nt][1];
            sumB += s[nt][2] + s[nt][3];
        }
        sumA += __shfl_xor_sync(0xffffffffu, sumA, 1);
        sumA += __shfl_xor_sync(0xffffffffu, sumA, 2);
        sumB += __shfl_xor_sync(0xffffffffu, sumB, 1);
        sumB += __shfl_xor_sync(0xffffffffu, sumB, 2);
        lA = lA * facA + sumA;
        lB = lB * facB + sumB;
        mA = mAn; mB = mBn;
#pragma unroll
        for (int dn = 0; dn < 8; dn++) {
            acc_o[dn][0] *= facA; acc_o[dn][1] *= facA;
            acc_o[dn][2] *= facB; acc_o[dn][3] *= facB;
        }

        // ---- O += P V (split, 3 passes) ----
#pragma unroll
        for (int kt = 0; kt < 4; kt++) {
            uint32_t Ph[4], Pl[4];
            Ph[0] = pack_bf16x2(s[2 * kt][0], s[2 * kt][1]);
            Ph[1] = pack_bf16x2(s[2 * kt][2], s[2 * kt][3]);
            Ph[2] = pack_bf16x2(s[2 * kt + 1][0], s[2 * kt + 1][1]);
            Ph[3] = pack_bf16x2(s[2 * kt + 1][2], s[2 * kt + 1][3]);
            Pl[0] = pack_bf16x2(s[2 * kt][0] - bf16lo(Ph[0]), s[2 * kt][1] - bf16hi(Ph[0]));
            Pl[1] = pack_bf16x2(s[2 * kt][2] - bf16lo(Ph[1]), s[2 * kt][3] - bf16hi(Ph[1]));
            Pl[2] = pack_bf16x2(s[2 * kt + 1][0] - bf16lo(Ph[2]), s[2 * kt + 1][1] - bf16hi(Ph[2]));
            Pl[3] = pack_bf16x2(s[2 * kt + 1][2] - bf16lo(Ph[3]), s[2 * kt + 1][3] - bf16hi(Ph[3]));
#pragma unroll
            for (int dp = 0; dp < 4; dp++) {
                uint32_t off = st + 2 * ABUF
                             + ((kt * 16 + ((lane >> 3) & 1) * 8 + (lane & 7)) * 72
                                + dp * 16 + (lane >> 4) * 8) * 2;
                uint32_t vh[4], vl[4];
                ldsm_x4t(vh, off);
                ldsm_x4t(vl, off + ABUF);
                mma_bf16(acc_o[2 * dp],     Ph, vh);
                mma_bf16(acc_o[2 * dp],     Ph, vl);
                mma_bf16(acc_o[2 * dp],     Pl, vh);
                mma_bf16(acc_o[2 * dp + 1], Ph, vh + 2);
                mma_bf16(acc_o[2 * dp + 1], Ph, vl + 2);
                mma_bf16(acc_o[2 * dp + 1], Pl, vh + 2);
            }
        }
        __syncthreads();
    }

    // ---- normalize + store fp32 ----
    float invA = 1.0f / lA, invB = 1.0f / lB;
    int rA = tok0 + q0 + wid * 16 + (lane >> 2);
#pragma unroll
    for (int dn = 0; dn < 8; dn++) {
        int col = hoff + dn * 8 + (lane & 3) * 2;
        float2 v0 = {acc_o[dn][0] * invA, acc_o[dn][1] * invA};
        float2 v1 = {acc_o[dn][2] * invB, acc_o[dn][3] * invB};
        *(float2*)&O[(size_t)rA * D_MODEL + col] = v0;
        *(float2*)&O[(size_t)(rA + 8) * D_MODEL + col] = v1;
    }
}

// ---------------------------------------------------------------------------
// Subtract projection; writes bf16 hi/lo directly for the final GEMM.
// ---------------------------------------------------------------------------
__global__ void subtract_proj(const float* __restrict__ O, const float* __restrict__ V,
                              const float* __restrict__ xsa,
                              __nv_bfloat16* __restrict__ oh, __nv_bfloat16* __restrict__ ol,
                              int tokens) {
    int gw = (blockIdx.x * blockDim.x + threadIdx.x) >> 5;
    int lane = threadIdx.x & 31;
    if (gw >= tokens * NUM_HEADS) return;
    int t = gw >> 4;
    int h = gw & 15;
    size_t base = (size_t)t * D_MODEL + h * HEAD_DIM;
    const float* v = V + base;
    const float* o = O + base;

    float o0 = o[lane], o1 = o[lane + 32];
    float v0 = v[lane], v1 = v[lane + 32];
    float dot = o0 * v0 + o1 * v1;
    float vn = v0 * v0 + v1 * v1;
#pragma unroll
    for (int off = 16; off > 0; off >>= 1) {
        dot += __shfl_xor_sync(0xffffffffu, dot, off);
        vn  += __shfl_xor_sync(0xffffffffu, vn, off);
    }
    float sc = xsa[0] * dot / (vn + 1e-8f);
    float r0 = o0 - sc * v0;
    float r1 = o1 - sc * v1;
    __nv_bfloat16 h0 = __float2bfloat16(r0);
    __nv_bfloat16 h1 = __float2bfloat16(r1);
    oh[base + lane] = h0;
    oh[base + lane + 32] = h1;
    ol[base + lane] = __float2bfloat16(r0 - __bfloat162float(h0));
    ol[base + lane + 32] = __float2bfloat16(r1 - __bfloat162float(h1));
}

// ---------------------------------------------------------------------------
// Launch
// ---------------------------------------------------------------------------
extern "C" void kernel_launch(void* const* d_in, const int* in_sizes, int n_in,
                              void* d_out, int out_size) {
    const float* x   = (const float*)d_in[0];
    const float* Wq  = (const float*)d_in[1];
    const float* Wk  = (const float*)d_in[2];
    const float* Wv  = (const float*)d_in[3];
    const float* Wo  = (const float*)d_in[4];
    const float* xsa = (const float*)d_in[5];

    const int M = in_sizes[0] / D_MODEL;   // 4096
    const int B = 2;
    const int S = M / B;                   // 2048

    float *v, *o;
    cudaGetSymbolAddress((void**)&v, g_v);
    cudaGetSymbolAddress((void**)&o, g_o);

    __nv_bfloat16 *xh, *xl, *qh, *ql, *kh, *kl, *vh, *vl, *oh, *ol;
    __nv_bfloat16 *wqh, *wql, *wkh, *wkl, *wvh, *wvl, *woh, *wol;
    cudaGetSymbolAddress((void**)&xh, g_xh);
    cudaGetSymbolAddress((void**)&xl, g_xl);
    cudaGetSymbolAddress((void**)&qh, g_qh);
    cudaGetSymbolAddress((void**)&ql, g_ql);
    cudaGetSymbolAddress((void**)&kh, g_kh);
    cudaGetSymbolAddress((void**)&kl, g_kl);
    cudaGetSymbolAddress((void**)&vh, g_vh);
    cudaGetSymbolAddress((void**)&vl, g_vl);
    cudaGetSymbolAddress((void**)&oh, g_oh);
    cudaGetSymbolAddress((void**)&ol, g_ol);
    cudaGetSymbolAddress((void**)&wqh, g_wqh);
    cudaGetSymbolAddress((void**)&wql, g_wql);
    cudaGetSymbolAddress((void**)&wkh, g_wkh);
    cudaGetSymbolAddress((void**)&wkl, g_wkl);
    cudaGetSymbolAddress((void**)&wvh, g_wvh);
    cudaGetSymbolAddress((void**)&wvl, g_wvl);
    cudaGetSymbolAddress((void**)&woh, g_woh);
    cudaGetSymbolAddress((void**)&wol, g_wol);

    static int attr_set = 0;
    if (!attr_set) {
        cudaFuncSetAttribute(gemm_mma, cudaFuncAttributeMaxDynamicSharedMemorySize,
                             2 * GSTAGE);
        cudaFuncSetAttribute(attn_mma, cudaFuncAttributeMaxDynamicSharedMemorySize,
                             ATT_SMEM);
        attr_set = 1;
    }

    const int nx = M * D_MODEL;
    const int nw = D_MODEL * D_MODEL;

    split_bf16<<<nx / 1024, 256>>>(x, xh, xl, nx);
    dim3 gw4(nw / 1024, 4);
    split_bf16_w4<<<gw4, 256>>>(Wq, Wk, Wv, Wo, wqh, wql, wkh, wkl,
                                wvh, wvl, woh, wol, nw);

    dim3 gg(D_MODEL / 128, M / 128);   // (8, 32)
    gemm_mma<<<gg, 256, 2 * GSTAGE>>>(xh, xl, wqh, wql, nullptr, qh, ql, M, D_MODEL, D_MODEL);
    gemm_mma<<<gg, 256, 2 * GSTAGE>>>(xh, xl, wkh, wkl, nullptr, kh, kl, M, D_MODEL, D_MODEL);
    gemm_mma<<<gg, 256, 2 * GSTAGE>>>(xh, xl, wvh, wvl, v, vh, vl, M, D_MODEL, D_MODEL);

    dim3 gattn(S / 128, NUM_HEADS, B);   // (16, 16, 2)
    attn_mma<<<gattn, 256, ATT_SMEM>>>(qh, ql, kh, kl, vh, vl, o, S);

    int warps = M * NUM_HEADS;
    subtract_proj<<<(warps * 32 + 255) / 256, 256>>>(o, v, xsa, oh, ol, M);

    gemm_mma<<<gg, 256, 2 * GSTAGE>>>(oh, ol, woh, wol, (float*)d_out, nullptr, nullptr,
                                      M, D_MODEL, D_MODEL);
}

// round 5
// speedup vs baseline: 1.1816x; 1.1816x over previous
#include <cuda_runtime.h>
#include <cuda_bf16.h>
#include <math.h>
#include <stdint.h>

#define D_MODEL   1024
#define NUM_HEADS 16
#define HEAD_DIM  64
#define NTOK      4096
// (1/sqrt(64)) * log2(e)
#define C_SCALE   0.18033688011112042f

// ---------------- static scratch (allocation-free rule) ----------------
__device__ float g_v[NTOK * D_MODEL];
__device__ float g_o[NTOK * D_MODEL];

__device__ __nv_bfloat16 g_xh[NTOK * D_MODEL];
__device__ __nv_bfloat16 g_xl[NTOK * D_MODEL];
__device__ __nv_bfloat16 g_qh[NTOK * D_MODEL];
__device__ __nv_bfloat16 g_ql[NTOK * D_MODEL];
__device__ __nv_bfloat16 g_kh[NTOK * D_MODEL];
__device__ __nv_bfloat16 g_kl[NTOK * D_MODEL];
__device__ __nv_bfloat16 g_vh[NTOK * D_MODEL];
__device__ __nv_bfloat16 g_vl[NTOK * D_MODEL];
__device__ __nv_bfloat16 g_oh[NTOK * D_MODEL];
__device__ __nv_bfloat16 g_ol[NTOK * D_MODEL];
__device__ __nv_bfloat16 g_wqh[D_MODEL * D_MODEL];
__device__ __nv_bfloat16 g_wql[D_MODEL * D_MODEL];
__device__ __nv_bfloat16 g_wkh[D_MODEL * D_MODEL];
__device__ __nv_bfloat16 g_wkl[D_MODEL * D_MODEL];
__device__ __nv_bfloat16 g_wvh[D_MODEL * D_MODEL];
__device__ __nv_bfloat16 g_wvl[D_MODEL * D_MODEL];
__device__ __nv_bfloat16 g_woh[D_MODEL * D_MODEL];
__device__ __nv_bfloat16 g_wol[D_MODEL * D_MODEL];

// ---------------- helpers ----------------
__device__ __forceinline__ uint32_t smem_u32(const void* p) {
    uint32_t a;
    asm("{ .reg .u64 t; cvta.to.shared.u64 t, %1; cvt.u32.u64 %0, t; }"
        : "=r"(a) : "l"(p));
    return a;
}

__device__ __forceinline__ void ldsm_x4(uint32_t* r, uint32_t addr) {
    asm volatile("ldmatrix.sync.aligned.m8n8.x4.shared.b16 {%0,%1,%2,%3}, [%4];"
                 : "=r"(r[0]), "=r"(r[1]), "=r"(r[2]), "=r"(r[3]) : "r"(addr));
}
__device__ __forceinline__ void ldsm_x4t(uint32_t* r, uint32_t addr) {
    asm volatile("ldmatrix.sync.aligned.m8n8.x4.trans.shared.b16 {%0,%1,%2,%3}, [%4];"
                 : "=r"(r[0]), "=r"(r[1]), "=r"(r[2]), "=r"(r[3]) : "r"(addr));
}
__device__ __forceinline__ void mma_bf16(float* d, const uint32_t* a, const uint32_t* b) {
    asm volatile(
        "mma.sync.aligned.m16n8k16.row.col.f32.bf16.bf16.f32 "
        "{%0,%1,%2,%3}, {%4,%5,%6,%7}, {%8,%9}, {%0,%1,%2,%3};"
        : "+f"(d[0]), "+f"(d[1]), "+f"(d[2]), "+f"(d[3])
        : "r"(a[0]), "r"(a[1]), "r"(a[2]), "r"(a[3]), "r"(b[0]), "r"(b[1]));
}

#define CP_ASYNC16(dst, src) \
    asm volatile("cp.async.cg.shared.global [%0], [%1], 16;" :: "r"(dst), "l"(src))
#define CP_COMMIT asm volatile("cp.async.commit_group;" ::: "memory")
template <int N>
__device__ __forceinline__ void cp_wait() {
    asm volatile("cp.async.wait_group %0;" :: "n"(N) : "memory");
}

__device__ __forceinline__ uint32_t pack_bf16x2(float lo, float hi) {
    __nv_bfloat162 t = __floats2bfloat162_rn(lo, hi);
    return *(uint32_t*)&t;
}
__device__ __forceinline__ float bf16lo(uint32_t p) { return __uint_as_float(p << 16); }
__device__ __forceinline__ float bf16hi(uint32_t p) { return __uint_as_float(p & 0xffff0000u); }

// fast 2^t on FMA pipe (t <= 0 expected), rel err < 2e-5
__device__ __forceinline__ float exp2_fast(float t) {
    t = fmaxf(t, -126.0f);
    float fn = floorf(t);
    float f = t - fn;
    float p = fmaf(f, 0.000154035f, 0.0013333558f);
    p = fmaf(f, p, 0.0096181291f);
    p = fmaf(f, p, 0.0555041087f);
    p = fmaf(f, p, 0.2402265070f);
    p = fmaf(f, p, 0.6931471806f);
    p = fmaf(f, p, 1.0f);
    int n = (int)fn;
    return p * __int_as_float((n + 127) << 23);
}

// ---------------------------------------------------------------------------
// fp32 -> (bf16 hi, bf16 lo) split
// ---------------------------------------------------------------------------
__device__ __forceinline__ void split_body(const float* __restrict__ x,
                                           __nv_bfloat16* __restrict__ h,
                                           __nv_bfloat16* __restrict__ l, int i) {
    float4 v = *(const float4*)(x + i);
    __nv_bfloat16 h0 = __float2bfloat16(v.x);
    __nv_bfloat16 h1 = __float2bfloat16(v.y);
    __nv_bfloat16 h2 = __float2bfloat16(v.z);
    __nv_bfloat16 h3 = __float2bfloat16(v.w);
    __nv_bfloat16 l0 = __float2bfloat16(v.x - __bfloat162float(h0));
    __nv_bfloat16 l1 = __float2bfloat16(v.y - __bfloat162float(h1));
    __nv_bfloat16 l2 = __float2bfloat16(v.z - __bfloat162float(h2));
    __nv_bfloat16 l3 = __float2bfloat16(v.w - __bfloat162float(h3));
    __nv_bfloat162* hp = (__nv_bfloat162*)(h + i);
    __nv_bfloat162* lp = (__nv_bfloat162*)(l + i);
    hp[0] = __nv_bfloat162(h0, h1); hp[1] = __nv_bfloat162(h2, h3);
    lp[0] = __nv_bfloat162(l0, l1); lp[1] = __nv_bfloat162(l2, l3);
}

__global__ void split_bf16(const float* __restrict__ x, __nv_bfloat16* __restrict__ h,
                           __nv_bfloat16* __restrict__ l, int n) {
    int i = (blockIdx.x * blockDim.x + threadIdx.x) * 4;
    if (i < n) split_body(x, h, l, i);
}

__global__ void split_bf16_w4(const float* w0, const float* w1, const float* w2,
                              const float* w3, __nv_bfloat16* h0, __nv_bfloat16* l0,
                              __nv_bfloat16* h1, __nv_bfloat16* l1,
                              __nv_bfloat16* h2, __nv_bfloat16* l2,
                              __nv_bfloat16* h3, __nv_bfloat16* l3, int n) {
    const float* w[4] = {w0, w1, w2, w3};
    __nv_bfloat16* h[4] = {h0, h1, h2, h3};
    __nv_bfloat16* l[4] = {l0, l1, l2, l3};
    int m = blockIdx.y;
    int i = (blockIdx.x * blockDim.x + threadIdx.x) * 4;
    if (i < n) split_body(w[m], h[m], l[m], i);
}

// ---------------------------------------------------------------------------
// HMMA split-bf16 GEMM. __launch_bounds__(256,2): cap regs at 128 so two CTAs
// fit per SM (R4 profile showed reg-limited occupancy of 1 CTA/SM).
// ---------------------------------------------------------------------------
#define GSTAGE 40960
#define GTILE  10240

__global__ __launch_bounds__(256, 2)
void gemm_mma(const __nv_bfloat16* __restrict__ Ah, const __nv_bfloat16* __restrict__ Al,
              const __nv_bfloat16* __restrict__ Bh, const __nv_bfloat16* __restrict__ Bl,
              float* __restrict__ C, __nv_bfloat16* __restrict__ Ch,
              __nv_bfloat16* __restrict__ Cl, int M, int N, int K) {
    extern __shared__ char smem[];
    const uint32_t sb = smem_u32(smem);
    const int tid = threadIdx.x;
    const int lane = tid & 31;
    const int wid = tid >> 5;
    const int wm = wid & 3;
    const int wn = wid >> 2;
    const int m0 = blockIdx.y * 128;
    const int n0 = blockIdx.x * 128;

    const __nv_bfloat16* srcs[4] = {Ah + (size_t)m0 * K, Al + (size_t)m0 * K,
                                    Bh + (size_t)n0 * K, Bl + (size_t)n0 * K};

    float acc[2][8][4];
#pragma unroll
    for (int a = 0; a < 2; a++)
#pragma unroll
        for (int b = 0; b < 8; b++)
#pragma unroll
            for (int c = 0; c < 4; c++) acc[a][b][c] = 0.f;

    auto load_stage = [&](int s, int kc) {
        uint32_t base = sb + s * GSTAGE;
#pragma unroll
        for (int t = 0; t < 4; t++) {
#pragma unroll
            for (int i = 0; i < 2; i++) {
                int seg = tid + i * 256;
                int row = seg >> 2;
                int cs = seg & 3;
                const void* src = srcs[t] + (size_t)row * K + kc * 32 + cs * 8;
                uint32_t dst = base + t * GTILE + (row * 40 + cs * 8) * 2;
                CP_ASYNC16(dst, src);
            }
        }
    };

    const int NCH = K / 32;
    load_stage(0, 0);
    CP_COMMIT;

    for (int kc = 0; kc < NCH; kc++) {
        if (kc + 1 < NCH) {
            load_stage((kc + 1) & 1, kc + 1);
            CP_COMMIT;
            cp_wait<1>();
        } else {
            cp_wait<0>();
        }
        __syncthreads();

        const uint32_t st = sb + (kc & 1) * GSTAGE;
#pragma unroll
        for (int kk = 0; kk < 32; kk += 16) {
            uint32_t a_h[2][4], a_l[2][4];
#pragma unroll
            for (int mt = 0; mt < 2; mt++) {
                uint32_t ar = st + ((wm * 32 + mt * 16 + (lane & 15)) * 40
                                    + kk + (lane >> 4) * 8) * 2;
                ldsm_x4(a_h[mt], ar);
                ldsm_x4(a_l[mt], ar + GTILE);
            }
#pragma unroll
            for (int np = 0; np < 4; np++) {
                uint32_t br = st + 2 * GTILE
                            + ((wn * 64 + np * 16 + ((lane >> 4) << 3) + (lane & 7)) * 40
                               + kk + ((lane >> 3) & 1) * 8) * 2;
                uint32_t bh[4], bl[4];
                ldsm_x4(bh, br);
                ldsm_x4(bl, br + GTILE);
#pragma unroll
                for (int mt = 0; mt < 2; mt++) {
                    mma_bf16(acc[mt][2 * np],     a_h[mt], bh);
                    mma_bf16(acc[mt][2 * np],     a_h[mt], bl);
                    mma_bf16(acc[mt][2 * np],     a_l[mt], bh);
                    mma_bf16(acc[mt][2 * np + 1], a_h[mt], bh + 2);
                    mma_bf16(acc[mt][2 * np + 1], a_h[mt], bl + 2);
                    mma_bf16(acc[mt][2 * np + 1], a_l[mt], bh + 2);
                }
            }
        }
        __syncthreads();
    }

#pragma unroll
    for (int mt = 0; mt < 2; mt++) {
#pragma unroll
        for (int nt = 0; nt < 8; nt++) {
            int r0 = m0 + wm * 32 + mt * 16 + (lane >> 2);
            int col = n0 + wn * 64 + nt * 8 + (lane & 3) * 2;
            float d0 = acc[mt][nt][0], d1 = acc[mt][nt][1];
            float d2 = acc[mt][nt][2], d3 = acc[mt][nt][3];
            if (C) {
                float2 v0 = {d0, d1}, v1 = {d2, d3};
                *(float2*)&C[(size_t)r0 * N + col] = v0;
                *(float2*)&C[(size_t)(r0 + 8) * N + col] = v1;
            }
            if (Ch) {
                uint32_t ph0 = pack_bf16x2(d0, d1);
                uint32_t pl0 = pack_bf16x2(d0 - bf16lo(ph0), d1 - bf16hi(ph0));
                uint32_t ph1 = pack_bf16x2(d2, d3);
                uint32_t pl1 = pack_bf16x2(d2 - bf16lo(ph1), d3 - bf16hi(ph1));
                *(uint32_t*)&Ch[(size_t)r0 * N + col] = ph0;
                *(uint32_t*)&Cl[(size_t)r0 * N + col] = pl0;
                *(uint32_t*)&Ch[(size_t)(r0 + 8) * N + col] = ph1;
                *(uint32_t*)&Cl[(size_t)(r0 + 8) * N + col] = pl1;
            }
        }
    }
}

// ---------------------------------------------------------------------------
// HMMA flash attention — R3-exact version (64-q blocks, 128 thr, static smem)
// ---------------------------------------------------------------------------
__global__ __launch_bounds__(128)
void attn_mma(const __nv_bfloat16* __restrict__ Qh_, const __nv_bfloat16* __restrict__ Ql_,
              const __nv_bfloat16* __restrict__ Kh_, const __nv_bfloat16* __restrict__ Kl_,
              const __nv_bfloat16* __restrict__ Vh_, const __nv_bfloat16* __restrict__ Vl_,
              float* __restrict__ O, int S) {
    __shared__ __align__(16) uint16_t sKh[64 * 72];
    __shared__ __align__(16) uint16_t sKl[64 * 72];
    __shared__ __align__(16) uint16_t sVh[64 * 72];
    __shared__ __align__(16) uint16_t sVl[64 * 72];

    const int tid = threadIdx.x;
    const int lane = tid & 31;
    const int wid = tid >> 5;
    const int h = blockIdx.y;
    const int b = blockIdx.z;
    const int q0 = blockIdx.x * 64;
    const int tok0 = b * S;
    const int hoff = h * HEAD_DIM;

    const uint32_t aKh = smem_u32(sKh), aKl = smem_u32(sKl);
    const uint32_t aVh = smem_u32(sVh), aVl = smem_u32(sVl);

#pragma unroll
    for (int i = 0; i < 4; i++) {
        int seg = tid + i * 128;
        int row = seg >> 3;
        int cs = seg & 7;
        const void* sh = Qh_ + (size_t)(tok0 + q0 + row) * D_MODEL + hoff + cs * 8;
        const void* sl = Ql_ + (size_t)(tok0 + q0 + row) * D_MODEL + hoff + cs * 8;
        CP_ASYNC16(aKh + (row * 72 + cs * 8) * 2, sh);
        CP_ASYNC16(aKl + (row * 72 + cs * 8) * 2, sl);
    }
    CP_COMMIT;
    cp_wait<0>();
    __syncthreads();

    uint32_t qh[4][4], ql[4][4];
#pragma unroll
    for (int kt = 0; kt < 4; kt++) {
        uint32_t off = ((wid * 16 + (lane & 15)) * 72 + kt * 16 + (lane >> 4) * 8) * 2;
        ldsm_x4(qh[kt], aKh + off);
        ldsm_x4(ql[kt], aKl + off);
    }
    __syncthreads();

    float acc_o[8][4];
#pragma unroll
    for (int i = 0; i < 8; i++)
#pragma unroll
        for (int j = 0; j < 4; j++) acc_o[i][j] = 0.f;
    float mA = -1e30f, mB = -1e30f, lA = 0.f, lB = 0.f;

    for (int c0 = 0; c0 < S; c0 += 64) {
#pragma unroll
        for (int i = 0; i < 4; i++) {
            int seg = tid + i * 128;
            int row = seg >> 3;
            int cs = seg & 7;
            size_t g = (size_t)(tok0 + c0 + row) * D_MODEL + hoff + cs * 8;
            uint32_t d = (row * 72 + cs * 8) * 2;
            CP_ASYNC16(aKh + d, Kh_ + g);
            CP_ASYNC16(aKl + d, Kl_ + g);
            CP_ASYNC16(aVh + d, Vh_ + g);
            CP_ASYNC16(aVl + d, Vl_ + g);
        }
        CP_COMMIT;
        cp_wait<0>();
        __syncthreads();

        float s[8][4];
#pragma unroll
        for (int i = 0; i < 8; i++)
#pragma unroll
            for (int j = 0; j < 4; j++) s[i][j] = 0.f;

#pragma unroll
        for (int kt = 0; kt < 4; kt++) {
#pragma unroll
            for (int np = 0; np < 4; np++) {
                uint32_t off = ((np * 16 + ((lane >> 4) << 3) + (lane & 7)) * 72
                                + kt * 16 + ((lane >> 3) & 1) * 8) * 2;
                uint32_t bh[4], bl[4];
                ldsm_x4(bh, aKh + off);
                ldsm_x4(bl, aKl + off);
                mma_bf16(s[2 * np],     qh[kt], bh);
                mma_bf16(s[2 * np],     qh[kt], bl);
                mma_bf16(s[2 * np],     ql[kt], bh);
                mma_bf16(s[2 * np + 1], qh[kt], bh + 2);
                mma_bf16(s[2 * np + 1], qh[kt], bl + 2);
                mma_bf16(s[2 * np + 1], ql[kt], bh + 2);
            }
        }

        float mxA = -1e30f, mxB = -1e30f;
#pragma unroll
        for (int nt = 0; nt < 8; nt++) {
            s[nt][0] *= C_SCALE; s[nt][1] *= C_SCALE;
            s[nt][2] *= C_SCALE; s[nt][3] *= C_SCALE;
            mxA = fmaxf(mxA, fmaxf(s[nt][0], s[nt][1]));
            mxB = fmaxf(mxB, fmaxf(s[nt][2], s[nt][3]));
        }
        mxA = fmaxf(mxA, __shfl_xor_sync(0xffffffffu, mxA, 1));
        mxA = fmaxf(mxA, __shfl_xor_sync(0xffffffffu, mxA, 2));
        mxB = fmaxf(mxB, __shfl_xor_sync(0xffffffffu, mxB, 1));
        mxB = fmaxf(mxB, __shfl_xor_sync(0xffffffffu, mxB, 2));
        float mAn = fmaxf(mA, mxA);
        float mBn = fmaxf(mB, mxB);
        float facA = exp2_fast(mA - mAn);
        float facB = exp2_fast(mB - mBn);
        float sumA = 0.f, sumB = 0.f;
#pragma unroll
        for (int nt = 0; nt < 8; nt++) {
            s[nt][0] = exp2_fast(s[nt][0] - mAn);
            s[nt][1] = exp2_fast(s[nt][1] - mAn);
            s[nt][2] = exp2_fast(s[nt][2] - mBn);
            s[nt][3] = exp2_fast(s[nt][3] - mBn);
            sumA += s[nt][0] + s[nt][1];
            sumB += s[nt][2] + s[nt][3];
        }
        sumA += __shfl_xor_sync(0xffffffffu, sumA, 1);
        sumA += __shfl_xor_sync(0xffffffffu, sumA, 2);
        sumB += __shfl_xor_sync(0xffffffffu, sumB, 1);
        sumB += __shfl_xor_sync(0xffffffffu, sumB, 2);
        lA = lA * facA + sumA;
        lB = lB * facB + sumB;
        mA = mAn; mB = mBn;
#pragma unroll
        for (int dn = 0; dn < 8; dn++) {
            acc_o[dn][0] *= facA; acc_o[dn][1] *= facA;
            acc_o[dn][2] *= facB; acc_o[dn][3] *= facB;
        }

#pragma unroll
        for (int kt = 0; kt < 4; kt++) {
            uint32_t Ph[4], Pl[4];
            Ph[0] = pack_bf16x2(s[2 * kt][0], s[2 * kt][1]);
            Ph[1] = pack_bf16x2(s[2 * kt][2], s[2 * kt][3]);
            Ph[2] = pack_bf16x2(s[2 * kt + 1][0], s[2 * kt + 1][1]);
            Ph[3] = pack_bf16x2(s[2 * kt + 1][2], s[2 * kt + 1][3]);
            Pl[0] = pack_bf16x2(s[2 * kt][0] - bf16lo(Ph[0]), s[2 * kt][1] - bf16hi(Ph[0]));
            Pl[1] = pack_bf16x2(s[2 * kt][2] - bf16lo(Ph[1]), s[2 * kt][3] - bf16hi(Ph[1]));
            Pl[2] = pack_bf16x2(s[2 * kt + 1][0] - bf16lo(Ph[2]), s[2 * kt + 1][1] - bf16hi(Ph[2]));
            Pl[3] = pack_bf16x2(s[2 * kt + 1][2] - bf16lo(Ph[3]), s[2 * kt + 1][3] - bf16hi(Ph[3]));
#pragma unroll
            for (int dp = 0; dp < 4; dp++) {
                uint32_t off = ((kt * 16 + ((lane >> 3) & 1) * 8 + (lane & 7)) * 72
                                + dp * 16 + (lane >> 4) * 8) * 2;
                uint32_t vh[4], vl[4];
                ldsm_x4t(vh, aVh + off);
                ldsm_x4t(vl, aVl + off);
                mma_bf16(acc_o[2 * dp],     Ph, vh);
                mma_bf16(acc_o[2 * dp],     Ph, vl);
                mma_bf16(acc_o[2 * dp],     Pl, vh);
                mma_bf16(acc_o[2 * dp + 1], Ph, vh + 2);
                mma_bf16(acc_o[2 * dp + 1], Ph, vl + 2);
                mma_bf16(acc_o[2 * dp + 1], Pl, vh + 2);
            }
        }
        __syncthreads();
    }

    float invA = 1.0f / lA, invB = 1.0f / lB;
    int rA = tok0 + q0 + wid * 16 + (lane >> 2);
#pragma unroll
    for (int dn = 0; dn < 8; dn++) {
        int col = hoff + dn * 8 + (lane & 3) * 2;
        float2 v0 = {acc_o[dn][0] * invA, acc_o[dn][1] * invA};
        float2 v1 = {acc_o[dn][2] * invB, acc_o[dn][3] * invB};
        *(float2*)&O[(size_t)rA * D_MODEL + col] = v0;
        *(float2*)&O[(size_t)(rA + 8) * D_MODEL + col] = v1;
    }
}

// ---------------------------------------------------------------------------
// Subtract projection; writes bf16 hi/lo directly for the final GEMM.
// ---------------------------------------------------------------------------
__global__ void subtract_proj(const float* __restrict__ O, const float* __restrict__ V,
                              const float* __restrict__ xsa,
                              __nv_bfloat16* __restrict__ oh, __nv_bfloat16* __restrict__ ol,
                              int tokens) {
    int gw = (blockIdx.x * blockDim.x + threadIdx.x) >> 5;
    int lane = threadIdx.x & 31;
    if (gw >= tokens * NUM_HEADS) return;
    int t = gw >> 4;
    int h = gw & 15;
    size_t base = (size_t)t * D_MODEL + h * HEAD_DIM;
    const float* v = V + base;
    const float* o = O + base;

    float o0 = o[lane], o1 = o[lane + 32];
    float v0 = v[lane], v1 = v[lane + 32];
    float dot = o0 * v0 + o1 * v1;
    float vn = v0 * v0 + v1 * v1;
#pragma unroll
    for (int off = 16; off > 0; off >>= 1) {
        dot += __shfl_xor_sync(0xffffffffu, dot, off);
        vn  += __shfl_xor_sync(0xffffffffu, vn, off);
    }
    float sc = xsa[0] * dot / (vn + 1e-8f);
    float r0 = o0 - sc * v0;
    float r1 = o1 - sc * v1;
    __nv_bfloat16 h0 = __float2bfloat16(r0);
    __nv_bfloat16 h1 = __float2bfloat16(r1);
    oh[base + lane] = h0;
    oh[base + lane + 32] = h1;
    ol[base + lane] = __float2bfloat16(r0 - __bfloat162float(h0));
    ol[base + lane + 32] = __float2bfloat16(r1 - __bfloat162float(h1));
}

// ---------------------------------------------------------------------------
// Launch
// ---------------------------------------------------------------------------
extern "C" void kernel_launch(void* const* d_in, const int* in_sizes, int n_in,
                              void* d_out, int out_size) {
    const float* x   = (const float*)d_in[0];
    const float* Wq  = (const float*)d_in[1];
    const float* Wk  = (const float*)d_in[2];
    const float* Wv  = (const float*)d_in[3];
    const float* Wo  = (const float*)d_in[4];
    const float* xsa = (const float*)d_in[5];

    const int M = in_sizes[0] / D_MODEL;   // 4096
    const int B = 2;
    const int S = M / B;                   // 2048

    float *v, *o;
    cudaGetSymbolAddress((void**)&v, g_v);
    cudaGetSymbolAddress((void**)&o, g_o);

    __nv_bfloat16 *xh, *xl, *qh, *ql, *kh, *kl, *vh, *vl, *oh, *ol;
    __nv_bfloat16 *wqh, *wql, *wkh, *wkl, *wvh, *wvl, *woh, *wol;
    cudaGetSymbolAddress((void**)&xh, g_xh);
    cudaGetSymbolAddress((void**)&xl, g_xl);
    cudaGetSymbolAddress((void**)&qh, g_qh);
    cudaGetSymbolAddress((void**)&ql, g_ql);
    cudaGetSymbolAddress((void**)&kh, g_kh);
    cudaGetSymbolAddress((void**)&kl, g_kl);
    cudaGetSymbolAddress((void**)&vh, g_vh);
    cudaGetSymbolAddress((void**)&vl, g_vl);
    cudaGetSymbolAddress((void**)&oh, g_oh);
    cudaGetSymbolAddress((void**)&ol, g_ol);
    cudaGetSymbolAddress((void**)&wqh, g_wqh);
    cudaGetSymbolAddress((void**)&wql, g_wql);
    cudaGetSymbolAddress((void**)&wkh, g_wkh);
    cudaGetSymbolAddress((void**)&wkl, g_wkl);
    cudaGetSymbolAddress((void**)&wvh, g_wvh);
    cudaGetSymbolAddress((void**)&wvl, g_wvl);
    cudaGetSymbolAddress((void**)&woh, g_woh);
    cudaGetSymbolAddress((void**)&wol, g_wol);

    static int attr_set = 0;
    if (!attr_set) {
        cudaFuncSetAttribute(gemm_mma, cudaFuncAttributeMaxDynamicSharedMemorySize,
                             2 * GSTAGE);
        attr_set = 1;
    }

    const int nx = M * D_MODEL;
    const int nw = D_MODEL * D_MODEL;

    split_bf16<<<nx / 1024, 256>>>(x, xh, xl, nx);
    dim3 gw4(nw / 1024, 4);
    split_bf16_w4<<<gw4, 256>>>(Wq, Wk, Wv, Wo, wqh, wql, wkh, wkl,
                                wvh, wvl, woh, wol, nw);

    dim3 gg(D_MODEL / 128, M / 128);   // (8, 32)
    gemm_mma<<<gg, 256, 2 * GSTAGE>>>(xh, xl, wqh, wql, nullptr, qh, ql, M, D_MODEL, D_MODEL);
    gemm_mma<<<gg, 256, 2 * GSTAGE>>>(xh, xl, wkh, wkl, nullptr, kh, kl, M, D_MODEL, D_MODEL);
    gemm_mma<<<gg, 256, 2 * GSTAGE>>>(xh, xl, wvh, wvl, v, vh, vl, M, D_MODEL, D_MODEL);

    dim3 gattn(S / 64, NUM_HEADS, B);   // (32, 16, 2)
    attn_mma<<<gattn, 128>>>(qh, ql, kh, kl, vh, vl, o, S);

    int warps = M * NUM_HEADS;
    subtract_proj<<<(warps * 32 + 255) / 256, 256>>>(o, v, xsa, oh, ol, M);

    gemm_mma<<<gg, 256, 2 * GSTAGE>>>(oh, ol, woh, wol, (float*)d_out, nullptr, nullptr,
                                      M, D_MODEL, D_MODEL);
}